// round 2
// baseline (speedup 1.0000x reference)
#include <cuda_runtime.h>
#include <cuda_bf16.h>
#include <math.h>

// Problem constants
#define B_   4
#define N_   2048
#define DIM_ 1024
#define H_   16
#define D_   64
#define M_   (B_ * N_)          // 8192 rows
#define QKVN (3 * DIM_)         // 3072
#define SCALE_ 0.03125f         // 1024^-0.5

// ---------------- scratch (device globals; no allocation APIs) ----------------
__device__ float g_q[B_ * H_ * N_ * D_];     // [b,h,n,d]
__device__ float g_k[B_ * H_ * N_ * D_];
__device__ float g_v[B_ * H_ * N_ * D_];
__device__ float g_attn[M_ * DIM_];          // [b,n,h*d]

// ---------------- GEMM1: qkv = x @ w_qkv, scatter to q/k/v heads --------------
#define GBM 128
#define GBN 128
#define GBK 8
#define GTM 8
#define GTN 8

__global__ __launch_bounds__(256) void gemm_qkv_kernel(const float* __restrict__ X,
                                                       const float* __restrict__ W) {
    const int K = DIM_, NN = QKVN;
    __shared__ float As[GBK][GBM];
    __shared__ float Bs[GBK][GBN];
    const int cRow = blockIdx.y, cCol = blockIdx.x;
    const int tid = threadIdx.x;
    const int tr = tid >> 4, tc = tid & 15;
    const float* A  = X + (size_t)cRow * GBM * K;
    const float* Bg = W + (size_t)cCol * GBN;
    const int aRow = tid >> 1, aCol = (tid & 1) << 2;
    const int bRow = tid >> 5, bCol = (tid & 31) << 2;

    float acc[GTM][GTN];
    #pragma unroll
    for (int i = 0; i < GTM; i++)
        #pragma unroll
        for (int j = 0; j < GTN; j++) acc[i][j] = 0.f;
    float regM[GTM], regN[GTN];

    for (int k0 = 0; k0 < K; k0 += GBK) {
        float4 av = *reinterpret_cast<const float4*>(&A[(size_t)aRow * K + k0 + aCol]);
        As[aCol + 0][aRow] = av.x;
        As[aCol + 1][aRow] = av.y;
        As[aCol + 2][aRow] = av.z;
        As[aCol + 3][aRow] = av.w;
        *reinterpret_cast<float4*>(&Bs[bRow][bCol]) =
            *reinterpret_cast<const float4*>(&Bg[(size_t)(k0 + bRow) * NN + bCol]);
        __syncthreads();
        #pragma unroll
        for (int kk = 0; kk < GBK; kk++) {
            #pragma unroll
            for (int i = 0; i < GTM; i++) regM[i] = As[kk][tr * GTM + i];
            #pragma unroll
            for (int j = 0; j < GTN; j++) regN[j] = Bs[kk][tc * GTN + j];
            #pragma unroll
            for (int i = 0; i < GTM; i++)
                #pragma unroll
                for (int j = 0; j < GTN; j++)
                    acc[i][j] += regM[i] * regN[j];
        }
        __syncthreads();
    }

    // scatter epilogue: col in [0,3072) -> which (q/k/v), head, d
    const int colBase = cCol * GBN;
    const int which = colBase / DIM_;             // uniform per CTA (128 | 1024)
    float* dst = (which == 0) ? g_q : (which == 1) ? g_k : g_v;
    const int colLoc = colBase - which * DIM_;
    #pragma unroll
    for (int i = 0; i < GTM; i++) {
        const int m = cRow * GBM + tr * GTM + i;
        const int b = m >> 11, n = m & (N_ - 1);
        #pragma unroll
        for (int j = 0; j < GTN; j++) {
            const int c = colLoc + tc * GTN + j;
            const int h = c >> 6, d = c & 63;
            dst[((((size_t)b * H_ + h) * N_) + n) * D_ + d] = acc[i][j];
        }
    }
}

// ---------------- Flash attention: per (q-block of 64, b*h) -------------------
#define FS 68   // smem row stride (floats), 16B-aligned rows, conflict-breaking

extern __shared__ float fsm[];

__global__ __launch_bounds__(256) void flash_kernel() {
    float* Qs = fsm;
    float* Ks = fsm + 64 * FS;
    float* Vs = fsm + 2 * 64 * FS;
    float* Ps = fsm + 3 * 64 * FS;

    const int bh = blockIdx.y;   // 0..63
    const int qb = blockIdx.x;   // 0..31
    const float* Qp = g_q + ((size_t)bh * N_ + qb * 64) * D_;
    const float* Kp = g_k + (size_t)bh * N_ * D_;
    const float* Vp = g_v + (size_t)bh * N_ * D_;

    const int tid = threadIdx.x;
    const int tr = tid >> 4, tc = tid & 15;

    // load Q tile [64][64]
    #pragma unroll
    for (int o = 0; o < 4; o++) {
        int lin = o * 256 + tid;
        int row = lin >> 4, c4 = (lin & 15) << 2;
        *reinterpret_cast<float4*>(&Qs[row * FS + c4]) =
            *reinterpret_cast<const float4*>(&Qp[row * 64 + c4]);
    }

    float m_i[4], l_i[4];
    float4 Ov[4];
    #pragma unroll
    for (int i = 0; i < 4; i++) {
        m_i[i] = -1e30f;
        l_i[i] = 0.f;
        Ov[i] = make_float4(0.f, 0.f, 0.f, 0.f);
    }

    for (int kt = 0; kt < N_ / 64; kt++) {
        __syncthreads();   // prior-iter smem reads complete (also covers Q load)
        #pragma unroll
        for (int o = 0; o < 4; o++) {
            int lin = o * 256 + tid;
            int row = lin >> 4, c4 = (lin & 15) << 2;
            *reinterpret_cast<float4*>(&Ks[row * FS + c4]) =
                *reinterpret_cast<const float4*>(&Kp[(kt * 64 + row) * 64 + c4]);
            *reinterpret_cast<float4*>(&Vs[row * FS + c4]) =
                *reinterpret_cast<const float4*>(&Vp[(kt * 64 + row) * 64 + c4]);
        }
        __syncthreads();

        // S[i][j] = sum_d Q[tr*4+i][d] * K[tc*4+j][d]
        float s[4][4];
        #pragma unroll
        for (int i = 0; i < 4; i++)
            #pragma unroll
            for (int j = 0; j < 4; j++) s[i][j] = 0.f;

        #pragma unroll
        for (int kk = 0; kk < 64; kk += 4) {
            float4 qa[4], kb[4];
            #pragma unroll
            for (int i = 0; i < 4; i++)
                qa[i] = *reinterpret_cast<const float4*>(&Qs[(tr * 4 + i) * FS + kk]);
            #pragma unroll
            for (int j = 0; j < 4; j++)
                kb[j] = *reinterpret_cast<const float4*>(&Ks[(tc * 4 + j) * FS + kk]);
            #pragma unroll
            for (int i = 0; i < 4; i++)
                #pragma unroll
                for (int j = 0; j < 4; j++)
                    s[i][j] += qa[i].x * kb[j].x + qa[i].y * kb[j].y +
                               qa[i].z * kb[j].z + qa[i].w * kb[j].w;
        }

        // online softmax update
        #pragma unroll
        for (int i = 0; i < 4; i++) {
            #pragma unroll
            for (int j = 0; j < 4; j++) s[i][j] *= SCALE_;
            float mx = fmaxf(fmaxf(s[i][0], s[i][1]), fmaxf(s[i][2], s[i][3]));
            #pragma unroll
            for (int off = 8; off >= 1; off >>= 1)
                mx = fmaxf(mx, __shfl_xor_sync(0xffffffffu, mx, off));
            float mn = fmaxf(m_i[i], mx);
            float alpha = __expf(m_i[i] - mn);
            float rs = 0.f;
            #pragma unroll
            for (int j = 0; j < 4; j++) {
                s[i][j] = __expf(s[i][j] - mn);
                rs += s[i][j];
            }
            #pragma unroll
            for (int off = 8; off >= 1; off >>= 1)
                rs += __shfl_xor_sync(0xffffffffu, rs, off);
            l_i[i] = l_i[i] * alpha + rs;
            m_i[i] = mn;
            Ov[i].x *= alpha; Ov[i].y *= alpha; Ov[i].z *= alpha; Ov[i].w *= alpha;
            *reinterpret_cast<float4*>(&Ps[(tr * 4 + i) * FS + tc * 4]) =
                make_float4(s[i][0], s[i][1], s[i][2], s[i][3]);
        }
        __syncthreads();

        // O[i][tc*4..+4] += sum_j P[i][j] * V[j][tc*4..+4]
        #pragma unroll
        for (int j = 0; j < 64; j += 4) {
            float4 pa[4], vb[4];
            #pragma unroll
            for (int i = 0; i < 4; i++)
                pa[i] = *reinterpret_cast<const float4*>(&Ps[(tr * 4 + i) * FS + j]);
            #pragma unroll
            for (int jj = 0; jj < 4; jj++)
                vb[jj] = *reinterpret_cast<const float4*>(&Vs[(j + jj) * FS + tc * 4]);
            #pragma unroll
            for (int i = 0; i < 4; i++) {
                Ov[i].x += pa[i].x * vb[0].x + pa[i].y * vb[1].x + pa[i].z * vb[2].x + pa[i].w * vb[3].x;
                Ov[i].y += pa[i].x * vb[0].y + pa[i].y * vb[1].y + pa[i].z * vb[2].y + pa[i].w * vb[3].y;
                Ov[i].z += pa[i].x * vb[0].z + pa[i].y * vb[1].z + pa[i].z * vb[2].z + pa[i].w * vb[3].z;
                Ov[i].w += pa[i].x * vb[0].w + pa[i].y * vb[1].w + pa[i].z * vb[2].w + pa[i].w * vb[3].w;
            }
        }
    }

    // normalize + write to [b, n, h*64 + d] layout
    const int b = bh >> 4, h = bh & 15;
    #pragma unroll
    for (int i = 0; i < 4; i++) {
        float inv = 1.f / l_i[i];
        int n = qb * 64 + tr * 4 + i;
        float4 o = make_float4(Ov[i].x * inv, Ov[i].y * inv, Ov[i].z * inv, Ov[i].w * inv);
        *reinterpret_cast<float4*>(
            &g_attn[((size_t)b * N_ + n) * DIM_ + h * 64 + tc * 4]) = o;
    }
}

// ---------------- GEMM2: out = g_attn @ w_out + b_out ------------------------
__global__ __launch_bounds__(256) void gemm_out_kernel(const float* __restrict__ Wout,
                                                       const float* __restrict__ bias,
                                                       float* __restrict__ out) {
    const int K = DIM_, NN = DIM_;
    __shared__ float As[GBK][GBM];
    __shared__ float Bs[GBK][GBN];
    const int cRow = blockIdx.y, cCol = blockIdx.x;
    const int tid = threadIdx.x;
    const int tr = tid >> 4, tc = tid & 15;
    const float* A  = g_attn + (size_t)cRow * GBM * K;
    const float* Bg = Wout + (size_t)cCol * GBN;
    const int aRow = tid >> 1, aCol = (tid & 1) << 2;
    const int bRow = tid >> 5, bCol = (tid & 31) << 2;

    float acc[GTM][GTN];
    #pragma unroll
    for (int i = 0; i < GTM; i++)
        #pragma unroll
        for (int j = 0; j < GTN; j++) acc[i][j] = 0.f;
    float regM[GTM], regN[GTN];

    for (int k0 = 0; k0 < K; k0 += GBK) {
        float4 av = *reinterpret_cast<const float4*>(&A[(size_t)aRow * K + k0 + aCol]);
        As[aCol + 0][aRow] = av.x;
        As[aCol + 1][aRow] = av.y;
        As[aCol + 2][aRow] = av.z;
        As[aCol + 3][aRow] = av.w;
        *reinterpret_cast<float4*>(&Bs[bRow][bCol]) =
            *reinterpret_cast<const float4*>(&Bg[(size_t)(k0 + bRow) * NN + bCol]);
        __syncthreads();
        #pragma unroll
        for (int kk = 0; kk < GBK; kk++) {
            #pragma unroll
            for (int i = 0; i < GTM; i++) regM[i] = As[kk][tr * GTM + i];
            #pragma unroll
            for (int j = 0; j < GTN; j++) regN[j] = Bs[kk][tc * GTN + j];
            #pragma unroll
            for (int i = 0; i < GTM; i++)
                #pragma unroll
                for (int j = 0; j < GTN; j++)
                    acc[i][j] += regM[i] * regN[j];
        }
        __syncthreads();
    }

    #pragma unroll
    for (int i = 0; i < GTM; i++) {
        const int m = cRow * GBM + tr * GTM + i;
        #pragma unroll
        for (int j = 0; j < GTN; j += 4) {
            const int col = cCol * GBN + tc * GTN + j;
            float4 bv = *reinterpret_cast<const float4*>(&bias[col]);
            float4 o = make_float4(acc[i][j] + bv.x, acc[i][j + 1] + bv.y,
                                   acc[i][j + 2] + bv.z, acc[i][j + 3] + bv.w);
            *reinterpret_cast<float4*>(&out[(size_t)m * NN + col]) = o;
        }
    }
}

// ---------------- launch ------------------------------------------------------
extern "C" void kernel_launch(void* const* d_in, const int* in_sizes, int n_in,
                              void* d_out, int out_size) {
    const float* x     = (const float*)d_in[0];
    const float* w_qkv = (const float*)d_in[1];
    const float* w_out = (const float*)d_in[2];
    const float* b_out = (const float*)d_in[3];
    float* out = (float*)d_out;

    dim3 blk(256);

    dim3 g1(QKVN / GBN, M_ / GBM);   // (24, 64)
    gemm_qkv_kernel<<<g1, blk>>>(x, w_qkv);

    const int fl_smem = 4 * 64 * FS * sizeof(float);  // 69632 B
    cudaFuncSetAttribute(flash_kernel, cudaFuncAttributeMaxDynamicSharedMemorySize, fl_smem);
    dim3 g2(N_ / 64, B_ * H_);       // (32, 64)
    flash_kernel<<<g2, blk, fl_smem>>>();

    dim3 g3(DIM_ / GBN, M_ / GBM);   // (8, 64)
    gemm_out_kernel<<<g3, blk>>>(w_out, b_out, out);
}

// round 3
// speedup vs baseline: 3.4528x; 3.4528x over previous
#include <cuda_runtime.h>
#include <cuda_bf16.h>
#include <stdint.h>

#define B_   4
#define N_   2048
#define DIM_ 1024
#define H_   16
#define M_   8192
#define QKVN 3072
#define SCALE_ 0.03125f

typedef __nv_bfloat16 bf16;

// ---------------- bf16 hi/lo planes (device globals, no allocation) ----------
__device__ __align__(16) bf16 g_xh[M_*DIM_],   g_xl[M_*DIM_];
__device__ __align__(16) bf16 g_wqh[DIM_*QKVN], g_wql[DIM_*QKVN];
__device__ __align__(16) bf16 g_woh[DIM_*DIM_], g_wol[DIM_*DIM_];
__device__ __align__(16) bf16 g_qh[M_*DIM_], g_ql[M_*DIM_];  // [b,h,n,d], Q pre-scaled
__device__ __align__(16) bf16 g_kh[M_*DIM_], g_kl[M_*DIM_];
__device__ __align__(16) bf16 g_vh[M_*DIM_], g_vl[M_*DIM_];
__device__ __align__(16) bf16 g_ah[M_*DIM_], g_al[M_*DIM_];  // attn out [m][1024]

// ---------------- PTX helpers ----------------
#define CP16(d, s) asm volatile("cp.async.cg.shared.global [%0], [%1], 16;" :: "r"(d), "l"(s))
#define CPCOMMIT() asm volatile("cp.async.commit_group;")
#define CPWAIT0()  asm volatile("cp.async.wait_group 0;" ::: "memory")
#define LDSM4(r, a)  asm volatile("ldmatrix.sync.aligned.m8n8.x4.shared.b16 {%0,%1,%2,%3},[%4];" \
    : "=r"((r)[0]), "=r"((r)[1]), "=r"((r)[2]), "=r"((r)[3]) : "r"(a))
#define LDSM4T(r, a) asm volatile("ldmatrix.sync.aligned.m8n8.x4.trans.shared.b16 {%0,%1,%2,%3},[%4];" \
    : "=r"((r)[0]), "=r"((r)[1]), "=r"((r)[2]), "=r"((r)[3]) : "r"(a))
#define MMA(c, a, b0, b1) asm volatile( \
    "mma.sync.aligned.m16n8k16.row.col.f32.bf16.bf16.f32 {%0,%1,%2,%3},{%4,%5,%6,%7},{%8,%9},{%0,%1,%2,%3};" \
    : "+f"((c)[0]), "+f"((c)[1]), "+f"((c)[2]), "+f"((c)[3]) \
    : "r"((a)[0]), "r"((a)[1]), "r"((a)[2]), "r"((a)[3]), "r"(b0), "r"(b1))

__device__ __forceinline__ void split2(float x, float y, uint32_t& hi, uint32_t& lo) {
    __nv_bfloat162 h = __floats2bfloat162_rn(x, y);
    __nv_bfloat162 l = __floats2bfloat162_rn(x - __bfloat162float(h.x),
                                             y - __bfloat162float(h.y));
    hi = *reinterpret_cast<uint32_t*>(&h);
    lo = *reinterpret_cast<uint32_t*>(&l);
}

// ---------------- split fp32 -> hi/lo bf16 planes ----------------
__global__ __launch_bounds__(256) void split_kernel(const float4* __restrict__ src,
                                                    int n4, int which) {
    int i = blockIdx.x * 256 + threadIdx.x;
    if (i >= n4) return;
    uint32_t *hi, *lo;
    if (which == 0)      { hi = (uint32_t*)g_xh;  lo = (uint32_t*)g_xl;  }
    else if (which == 1) { hi = (uint32_t*)g_wqh; lo = (uint32_t*)g_wql; }
    else                 { hi = (uint32_t*)g_woh; lo = (uint32_t*)g_wol; }
    float4 v = src[i];
    uint32_t h0, l0, h1, l1;
    split2(v.x, v.y, h0, l0);
    split2(v.z, v.w, h1, l1);
    hi[i*2] = h0; hi[i*2+1] = h1;
    lo[i*2] = l0; lo[i*2+1] = l1;
}

// ---------------- MMA GEMM: C = A @ B (3-term bf16 split) --------------------
// MODE 0: A=g_x, B=g_wq, NN=3072, epilogue scatters split Q(scaled)/K/V planes
// MODE 1: A=g_a, B=g_wo, NN=1024, epilogue adds bias, writes fp32 out
template<int NN, int MODE>
__global__ __launch_bounds__(256) void mma_gemm(const float* __restrict__ bias,
                                                float* __restrict__ out) {
    const bf16* Agh = MODE ? g_ah  : g_xh;
    const bf16* Agl = MODE ? g_al  : g_xl;
    const bf16* Bgh = MODE ? g_woh : g_wqh;
    const bf16* Bgl = MODE ? g_wol : g_wql;

    extern __shared__ bf16 sm[];
    const int SA = 40, SB = 136;
    const int APL = 128 * SA;            // 5120 elems
    const int BPL = 32 * SB;             // 4352 elems
    const int STG = 2 * APL + 2 * BPL;   // per-stage elems

    const int tid = threadIdx.x;
    const int mBase = blockIdx.y * 128;
    const int nBase = blockIdx.x * 128;
    uint32_t sbase = (uint32_t)__cvta_generic_to_shared(sm);

    auto stage_load = [&](int k0, int buf) {
        uint32_t s0 = sbase + buf * STG * 2;
        #pragma unroll
        for (int p = 0; p < 2; p++) {
            const bf16* Ag = p ? Agl : Agh;
            uint32_t so = s0 + p * APL * 2;
            #pragma unroll
            for (int c = 0; c < 2; c++) {
                int ch = tid * 2 + c;              // 0..511
                int row = ch >> 2, kc = (ch & 3) * 8;
                CP16(so + (row * SA + kc) * 2,
                     Ag + (size_t)(mBase + row) * DIM_ + k0 + kc);
            }
        }
        #pragma unroll
        for (int p = 0; p < 2; p++) {
            const bf16* Bg = p ? Bgl : Bgh;
            uint32_t so = s0 + (2 * APL + p * BPL) * 2;
            #pragma unroll
            for (int c = 0; c < 2; c++) {
                int ch = tid * 2 + c;
                int row = ch >> 4, nc = (ch & 15) * 8;
                CP16(so + (row * SB + nc) * 2,
                     Bg + (size_t)(k0 + row) * NN + nBase + nc);
            }
        }
    };

    const int lane = tid & 31, wid = tid >> 5;
    const int wm = (wid & 3) * 32, wn = (wid >> 2) * 64;

    float c[16][4];
    #pragma unroll
    for (int i = 0; i < 16; i++)
        #pragma unroll
        for (int j = 0; j < 4; j++) c[i][j] = 0.f;

    stage_load(0, 0); CPCOMMIT();

    for (int ks = 0; ks < DIM_ / 32; ks++) {
        CPWAIT0(); __syncthreads();
        if (ks + 1 < DIM_ / 32) { stage_load((ks + 1) * 32, (ks + 1) & 1); CPCOMMIT(); }
        uint32_t s0 = sbase + (ks & 1) * STG * 2;
        #pragma unroll
        for (int kk = 0; kk < 32; kk += 16) {
            uint32_t ah[2][4], al[2][4];
            #pragma unroll
            for (int mi = 0; mi < 2; mi++) {
                int row = wm + mi * 16 + (lane & 15);
                uint32_t off = (row * SA + kk + (lane >> 4) * 8) * 2;
                LDSM4(ah[mi], s0 + off);
                LDSM4(al[mi], s0 + APL * 2 + off);
            }
            uint32_t bh[4][4], bl[4][4];
            #pragma unroll
            for (int g = 0; g < 4; g++) {
                int kr = kk + (lane & 7) + ((lane >> 3) & 1) * 8;
                int nc = wn + g * 16 + ((lane >> 4) & 1) * 8;
                uint32_t off = (kr * SB + nc) * 2;
                LDSM4T(bh[g], s0 + (2 * APL) * 2 + off);
                LDSM4T(bl[g], s0 + (2 * APL + BPL) * 2 + off);
            }
            #pragma unroll
            for (int mi = 0; mi < 2; mi++)
                #pragma unroll
                for (int g = 0; g < 4; g++) {
                    float* c0 = c[mi * 8 + g * 2];
                    float* c1 = c[mi * 8 + g * 2 + 1];
                    MMA(c0, ah[mi], bh[g][0], bh[g][1]);
                    MMA(c0, ah[mi], bl[g][0], bl[g][1]);
                    MMA(c0, al[mi], bh[g][0], bh[g][1]);
                    MMA(c1, ah[mi], bh[g][2], bh[g][3]);
                    MMA(c1, ah[mi], bl[g][2], bl[g][3]);
                    MMA(c1, al[mi], bh[g][2], bh[g][3]);
                }
        }
        __syncthreads();
    }

    // epilogue
    #pragma unroll
    for (int mi = 0; mi < 2; mi++)
        #pragma unroll
        for (int j = 0; j < 8; j++) {
            float* cc = c[mi * 8 + j];
            int col = nBase + wn + j * 8 + (lane & 3) * 2;
            #pragma unroll
            for (int h = 0; h < 2; h++) {
                int m = mBase + wm + mi * 16 + (lane >> 2) + h * 8;
                float v0 = cc[h * 2], v1 = cc[h * 2 + 1];
                if (MODE == 0) {
                    int which = col >> 10;
                    int cl = col & 1023;
                    if (which == 0) { v0 *= SCALE_; v1 *= SCALE_; }
                    uint32_t hv, lv;
                    split2(v0, v1, hv, lv);
                    int b = m >> 11, n = m & 2047;
                    int hh = cl >> 6, d = cl & 63;
                    size_t off = ((((size_t)b * H_ + hh) * N_) + n) * 64 + d;
                    bf16* dh = (which == 0) ? g_qh : (which == 1) ? g_kh : g_vh;
                    bf16* dl = (which == 0) ? g_ql : (which == 1) ? g_kl : g_vl;
                    *(uint32_t*)(dh + off) = hv;
                    *(uint32_t*)(dl + off) = lv;
                } else {
                    float2 bv = *(const float2*)(bias + col);
                    float2 o = make_float2(v0 + bv.x, v1 + bv.y);
                    *(float2*)(out + (size_t)m * DIM_ + col) = o;
                }
            }
        }
}

// ---------------- flash attention on MMA ----------------
// CTA: 128 thr (4 warps), q-tile 64 (warp = 16 q rows), key-tile 64, d=64
__global__ __launch_bounds__(128) void flash_mma() {
    extern __shared__ bf16 fsm[];
    const int SQ = 72;
    const int QPL = 64 * SQ;       // 4608 elems per plane
    const int KSTG = 4 * QPL;      // Kh,Kl,Vh,Vl per stage

    const int bh = blockIdx.y, qb = blockIdx.x;
    const int bb = bh >> 4, hh = bh & 15;
    const int tid = threadIdx.x, lane = tid & 31, wid = tid >> 5;
    uint32_t sb = (uint32_t)__cvta_generic_to_shared(fsm);

    const bf16* Qh = g_qh + ((size_t)bh * N_ + qb * 64) * 64;
    const bf16* Ql = g_ql + ((size_t)bh * N_ + qb * 64) * 64;
    const bf16* Kh = g_kh + (size_t)bh * N_ * 64;
    const bf16* Kl = g_kl + (size_t)bh * N_ * 64;
    const bf16* Vh = g_vh + (size_t)bh * N_ * 64;
    const bf16* Vl = g_vl + (size_t)bh * N_ * 64;

    // Q tiles resident
    #pragma unroll
    for (int p = 0; p < 2; p++) {
        const bf16* src = p ? Ql : Qh;
        #pragma unroll
        for (int c = 0; c < 4; c++) {
            int ch = tid * 4 + c;                     // 0..511
            int row = ch >> 3, kc = (ch & 7) * 8;
            CP16(sb + (p * QPL + row * SQ + kc) * 2, src + row * 64 + kc);
        }
    }
    auto kv_load = [&](int kt, int buf) {
        uint32_t s0 = sb + (2 * QPL + buf * KSTG) * 2;
        const bf16* srcs[4] = {Kh, Kl, Vh, Vl};
        #pragma unroll
        for (int p = 0; p < 4; p++)
            #pragma unroll
            for (int c = 0; c < 4; c++) {
                int ch = tid * 4 + c;
                int row = ch >> 3, kc = (ch & 7) * 8;
                CP16(s0 + (p * QPL + row * SQ + kc) * 2,
                     srcs[p] + (size_t)(kt * 64 + row) * 64 + kc);
            }
    };
    kv_load(0, 0); CPCOMMIT();

    float s[8][4], o[8][4];
    float mr[2] = {-1e30f, -1e30f}, lr[2] = {0.f, 0.f};
    #pragma unroll
    for (int j = 0; j < 8; j++)
        #pragma unroll
        for (int i = 0; i < 4; i++) o[j][i] = 0.f;

    for (int kt = 0; kt < N_ / 64; kt++) {
        CPWAIT0(); __syncthreads();
        if (kt + 1 < N_ / 64) { kv_load(kt + 1, (kt + 1) & 1); CPCOMMIT(); }
        uint32_t s0 = sb + (2 * QPL + (kt & 1) * KSTG) * 2;

        // S = Q K^T (3-term)
        #pragma unroll
        for (int j = 0; j < 8; j++)
            #pragma unroll
            for (int i = 0; i < 4; i++) s[j][i] = 0.f;
        #pragma unroll
        for (int kk = 0; kk < 64; kk += 16) {
            uint32_t qh[4], ql[4];
            {
                int row = wid * 16 + (lane & 15);
                uint32_t off = (row * SQ + kk + (lane >> 4) * 8) * 2;
                LDSM4(qh, sb + off);
                LDSM4(ql, sb + QPL * 2 + off);
            }
            #pragma unroll
            for (int g = 0; g < 4; g++) {
                uint32_t kbh[4], kbl[4];
                int kr = g * 16 + (lane & 7) + ((lane >> 3) & 1) * 8;
                uint32_t off = (kr * SQ + kk + (lane >> 4) * 8) * 2;
                LDSM4(kbh, s0 + off);
                LDSM4(kbl, s0 + QPL * 2 + off);
                float* c0 = s[g * 2];
                float* c1 = s[g * 2 + 1];
                MMA(c0, qh, kbh[0], kbh[2]);
                MMA(c0, qh, kbl[0], kbl[2]);
                MMA(c0, ql, kbh[0], kbh[2]);
                MMA(c1, qh, kbh[1], kbh[3]);
                MMA(c1, qh, kbl[1], kbl[3]);
                MMA(c1, ql, kbh[1], kbh[3]);
            }
        }

        // online softmax (rows: lane>>2 and +8; 4-lane groups share a row)
        #pragma unroll
        for (int h = 0; h < 2; h++) {
            float mx = -1e30f;
            #pragma unroll
            for (int j = 0; j < 8; j++)
                mx = fmaxf(mx, fmaxf(s[j][h * 2], s[j][h * 2 + 1]));
            mx = fmaxf(mx, __shfl_xor_sync(0xffffffffu, mx, 1));
            mx = fmaxf(mx, __shfl_xor_sync(0xffffffffu, mx, 2));
            float mn = fmaxf(mr[h], mx);
            float alpha = __expf(mr[h] - mn);
            mr[h] = mn;
            float rs = 0.f;
            #pragma unroll
            for (int j = 0; j < 8; j++) {
                s[j][h * 2]     = __expf(s[j][h * 2] - mn);
                s[j][h * 2 + 1] = __expf(s[j][h * 2 + 1] - mn);
                rs += s[j][h * 2] + s[j][h * 2 + 1];
            }
            rs += __shfl_xor_sync(0xffffffffu, rs, 1);
            rs += __shfl_xor_sync(0xffffffffu, rs, 2);
            lr[h] = lr[h] * alpha + rs;
            #pragma unroll
            for (int j = 0; j < 8; j++) {
                o[j][h * 2] *= alpha;
                o[j][h * 2 + 1] *= alpha;
            }
        }

        // O += P V (P split in registers)
        #pragma unroll
        for (int t = 0; t < 4; t++) {
            uint32_t pah[4], pal[4];
            split2(s[2 * t][0],     s[2 * t][1],     pah[0], pal[0]);
            split2(s[2 * t][2],     s[2 * t][3],     pah[1], pal[1]);
            split2(s[2 * t + 1][0], s[2 * t + 1][1], pah[2], pal[2]);
            split2(s[2 * t + 1][2], s[2 * t + 1][3], pah[3], pal[3]);
            #pragma unroll
            for (int g = 0; g < 4; g++) {
                uint32_t vbh[4], vbl[4];
                int kr = t * 16 + (lane & 7) + ((lane >> 3) & 1) * 8;
                uint32_t off = (kr * SQ + g * 16 + ((lane >> 4) & 1) * 8) * 2;
                LDSM4T(vbh, s0 + 2 * QPL * 2 + off);
                LDSM4T(vbl, s0 + 3 * QPL * 2 + off);
                float* o0 = o[g * 2];
                float* o1 = o[g * 2 + 1];
                MMA(o0, pah, vbh[0], vbh[1]);
                MMA(o0, pah, vbl[0], vbl[1]);
                MMA(o0, pal, vbh[0], vbh[1]);
                MMA(o1, pah, vbh[2], vbh[3]);
                MMA(o1, pah, vbl[2], vbl[3]);
                MMA(o1, pal, vbh[2], vbh[3]);
            }
        }
        __syncthreads();
    }

    // normalize + write split attn output at [b, n, h*64 + d]
    float inv0 = 1.f / lr[0], inv1 = 1.f / lr[1];
    #pragma unroll
    for (int j = 0; j < 8; j++) {
        int d0 = j * 8 + (lane & 3) * 2;
        #pragma unroll
        for (int h = 0; h < 2; h++) {
            int n = qb * 64 + wid * 16 + (lane >> 2) + h * 8;
            float inv = h ? inv1 : inv0;
            float v0 = o[j][h * 2] * inv, v1 = o[j][h * 2 + 1] * inv;
            uint32_t hv, lv;
            split2(v0, v1, hv, lv);
            size_t off = ((size_t)bb * N_ + n) * DIM_ + hh * 64 + d0;
            *(uint32_t*)(g_ah + off) = hv;
            *(uint32_t*)(g_al + off) = lv;
        }
    }
}

// ---------------- launch ----------------
extern "C" void kernel_launch(void* const* d_in, const int* in_sizes, int n_in,
                              void* d_out, int out_size) {
    const float* x     = (const float*)d_in[0];
    const float* w_qkv = (const float*)d_in[1];
    const float* w_out = (const float*)d_in[2];
    const float* b_out = (const float*)d_in[3];
    float* out = (float*)d_out;

    // 1. split inputs into bf16 hi/lo planes
    split_kernel<<<(M_*DIM_/4 + 255)/256, 256>>>((const float4*)x,     M_*DIM_/4,   0);
    split_kernel<<<(DIM_*QKVN/4 + 255)/256, 256>>>((const float4*)w_qkv, DIM_*QKVN/4, 1);
    split_kernel<<<(DIM_*DIM_/4 + 255)/256, 256>>>((const float4*)w_out, DIM_*DIM_/4, 2);

    const int gemm_smem = 2 * (2*128*40 + 2*32*136) * 2;   // 75776 B
    const int fl_smem   = (2*64*72 + 2*4*64*72) * 2;       // 92160 B

    // 2. QKV projection + head scatter
    cudaFuncSetAttribute(mma_gemm<QKVN,0>, cudaFuncAttributeMaxDynamicSharedMemorySize, gemm_smem);
    mma_gemm<QKVN,0><<<dim3(QKVN/128, M_/128), 256, gemm_smem>>>(nullptr, nullptr);

    // 3. flash attention
    cudaFuncSetAttribute(flash_mma, cudaFuncAttributeMaxDynamicSharedMemorySize, fl_smem);
    flash_mma<<<dim3(N_/64, B_*H_), 128, fl_smem>>>();

    // 4. output projection + bias
    cudaFuncSetAttribute(mma_gemm<DIM_,1>, cudaFuncAttributeMaxDynamicSharedMemorySize, gemm_smem);
    mma_gemm<DIM_,1><<<dim3(DIM_/128, M_/128), 256, gemm_smem>>>(b_out, out);
}